// round 12
// baseline (speedup 1.0000x reference)
#include <cuda_runtime.h>
#include <cuda_fp16.h>
#include <cstdint>

#define EPS 1e-5f

__device__ __forceinline__ float tanh_fast(float x) {
    float y; asm("tanh.approx.f32 %0,%1;" : "=f"(y) : "f"(x)); return y;
}
__device__ __forceinline__ unsigned tanh2(unsigned v) {
    unsigned y; asm("tanh.approx.f16x2 %0,%1;" : "=r"(y) : "r"(v)); return y;
}
__device__ __forceinline__ unsigned packh2(float a, float b) {
    __half2 h = __floats2half2_rn(a, b);
    return *reinterpret_cast<unsigned*>(&h);
}
__device__ __forceinline__ void barpair(int id) {
    asm volatile("bar.sync %0, 64;" :: "r"(id) : "memory");
}

__device__ __forceinline__ void mma16(float* d,
                                      unsigned a0, unsigned a1, unsigned a2, unsigned a3,
                                      unsigned b0, unsigned b1) {
    asm volatile(
        "mma.sync.aligned.m16n8k16.row.col.f32.f16.f16.f32 "
        "{%0,%1,%2,%3},{%4,%5,%6,%7},{%8,%9},{%0,%1,%2,%3};"
        : "+f"(d[0]), "+f"(d[1]), "+f"(d[2]), "+f"(d[3])
        : "r"(a0), "r"(a1), "r"(a2), "r"(a3), "r"(b0), "r"(b1));
}

__device__ __forceinline__ void ldsm4(unsigned& r0, unsigned& r1, unsigned& r2, unsigned& r3,
                                      unsigned addr) {
    asm volatile("ldmatrix.sync.aligned.m8n8.x4.shared.b16 {%0,%1,%2,%3},[%4];"
                 : "=r"(r0), "=r"(r1), "=r"(r2), "=r"(r3) : "r"(addr));
}

// hb row stride: 72 halfs = 36 u32 words (conflict-free for all access patterns used)
#define HSTRW 36

// d[mt][ntl][4]: this warp's N-half (global nt = 4*half + ntl)
__device__ __forceinline__ void init_bias(float d[2][4][4], const float* __restrict__ sb,
                                          int tg, int half) {
#pragma unroll
    for (int ntl = 0; ntl < 4; ntl++) {
        float2 bb = *(const float2*)&sb[8 * (4 * half + ntl) + 2 * tg];
        d[0][ntl][0] = bb.x; d[0][ntl][1] = bb.y; d[0][ntl][2] = bb.x; d[0][ntl][3] = bb.y;
        d[1][ntl][0] = bb.x; d[1][ntl][1] = bb.y; d[1][ntl][2] = bb.x; d[1][ntl][3] = bb.y;
    }
}

template <int NKK>
__device__ __forceinline__ void mma_layer(float d[2][4][4], const uint4* __restrict__ bf,
                                          unsigned a_base0, unsigned a_base1,
                                          int lane, int half) {
#pragma unroll
    for (int kk = 0; kk < NKK; kk++) {
        unsigned A[2][4];
        ldsm4(A[0][0], A[0][1], A[0][2], A[0][3], a_base0 + kk * 32);
        ldsm4(A[1][0], A[1][1], A[1][2], A[1][3], a_base1 + kk * 32);
#pragma unroll
        for (int np = 0; np < 2; np++) {   // ntp = 2*half + np -> ntl = 2np, 2np+1
            uint4 b = bf[(kk * 4 + 2 * half + np) * 32 + lane];
            mma16(d[0][2 * np],     A[0][0], A[0][1], A[0][2], A[0][3], b.x, b.y);
            mma16(d[1][2 * np],     A[1][0], A[1][1], A[1][2], A[1][3], b.x, b.y);
            mma16(d[0][2 * np + 1], A[0][0], A[0][1], A[0][2], A[0][3], b.z, b.w);
            mma16(d[1][2 * np + 1], A[1][0], A[1][1], A[1][2], A[1][3], b.z, b.w);
        }
    }
}

// Pair LN: partial stats over this warp's 32 cols, exchange via pstat, finish.
// STORE=true: tanh.f16x2 -> hb. STORE=false: f32 tanh in regs.
template <bool STORE>
__device__ __forceinline__ void ln_tanh_pair(float d[2][4][4],
                                             const float* __restrict__ sg,
                                             const float* __restrict__ sbe,
                                             unsigned* __restrict__ hbu,
                                             float* __restrict__ pstat,
                                             int g, int tg, int half, int barid) {
    float ps[2][4];
#pragma unroll
    for (int mt = 0; mt < 2; mt++) {
        float s1 = 0.f, q1 = 0.f, s2 = 0.f, q2 = 0.f;
#pragma unroll
        for (int ntl = 0; ntl < 4; ntl++) {
            float a = d[mt][ntl][0], b = d[mt][ntl][1];
            float c = d[mt][ntl][2], e = d[mt][ntl][3];
            s1 += a + b; q1 = fmaf(a, a, q1); q1 = fmaf(b, b, q1);
            s2 += c + e; q2 = fmaf(c, c, q2); q2 = fmaf(e, e, q2);
        }
        s1 += __shfl_xor_sync(0xffffffffu, s1, 1); q1 += __shfl_xor_sync(0xffffffffu, q1, 1);
        s2 += __shfl_xor_sync(0xffffffffu, s2, 1); q2 += __shfl_xor_sync(0xffffffffu, q2, 1);
        s1 += __shfl_xor_sync(0xffffffffu, s1, 2); q1 += __shfl_xor_sync(0xffffffffu, q1, 2);
        s2 += __shfl_xor_sync(0xffffffffu, s2, 2); q2 += __shfl_xor_sync(0xffffffffu, q2, 2);
        ps[mt][0] = s1; ps[mt][1] = q1; ps[mt][2] = s2; ps[mt][3] = q2;
        if (tg == 0)
            *(float4*)&pstat[half * 64 + mt * 32 + g * 4] =
                make_float4(s1, q1, s2, q2);
    }
    barpair(barid);   // stats visible
#pragma unroll
    for (int mt = 0; mt < 2; mt++) {
        float4 o = *(const float4*)&pstat[(1 - half) * 64 + mt * 32 + g * 4];
        float S1 = ps[mt][0] + o.x, Q1 = ps[mt][1] + o.y;
        float S2 = ps[mt][2] + o.z, Q2 = ps[mt][3] + o.w;
        float m1 = S1 * (1.f / 64.f), m2 = S2 * (1.f / 64.f);
        float i1 = rsqrtf(fmaf(-m1, m1, Q1 * (1.f / 64.f)) + EPS);
        float i2 = rsqrtf(fmaf(-m2, m2, Q2 * (1.f / 64.f)) + EPS);
#pragma unroll
        for (int ntl = 0; ntl < 4; ntl++) {
            int n0 = 8 * (4 * half + ntl) + 2 * tg;
            float2 gg = *(const float2*)&sg[n0];
            float2 bb = *(const float2*)&sbe[n0];
            float y0 = fmaf((d[mt][ntl][0] - m1) * i1, gg.x, bb.x);
            float y1 = fmaf((d[mt][ntl][1] - m1) * i1, gg.y, bb.y);
            float y2 = fmaf((d[mt][ntl][2] - m2) * i2, gg.x, bb.x);
            float y3 = fmaf((d[mt][ntl][3] - m2) * i2, gg.y, bb.y);
            if (STORE) {
                int w = 16 * half + 4 * ntl + tg;
                hbu[(16 * mt + g) * HSTRW + w]     = tanh2(packh2(y0, y1));
                hbu[(16 * mt + g + 8) * HSTRW + w] = tanh2(packh2(y2, y3));
            } else {
                d[mt][ntl][0] = tanh_fast(y0);
                d[mt][ntl][1] = tanh_fast(y1);
                d[mt][ntl][2] = tanh_fast(y2);
                d[mt][ntl][3] = tanh_fast(y3);
            }
        }
    }
}

// smem layout (float units):
// BF0 [512] @0 | BF1 [2048] @512 | BF2 [2048] @2560 | params @4608..5247
// hb @5248: 4 pairs x 32 rows x 36 words = 4608
// pstat @9856: 4 pairs x 128 = 512
// pdot @10368: 4 pairs x 64 = 256
#define SMEM_FLOATS 10624

__global__ __launch_bounds__(256, 3) void edge_mlp_tc(
    const float* __restrict__ x, const int* __restrict__ ei,
    const float* __restrict__ W0, const float* __restrict__ b0,
    const float* __restrict__ g0, const float* __restrict__ be0,
    const float* __restrict__ W1, const float* __restrict__ b1,
    const float* __restrict__ g1, const float* __restrict__ be1,
    const float* __restrict__ W2, const float* __restrict__ b2,
    const float* __restrict__ g2, const float* __restrict__ be2,
    const float* __restrict__ W3, const float* __restrict__ b3,
    float* __restrict__ out, int n_edges)
{
    extern __shared__ float sm[];
    uint4* BF0 = (uint4*)(sm);
    uint4* BF1 = (uint4*)(sm + 512);
    uint4* BF2 = (uint4*)(sm + 2560);
    float* sb0 = sm + 4608; float* sb1 = sm + 4672; float* sb2 = sm + 4736;
    float* sg0 = sm + 4800; float* sbe0 = sm + 4864;
    float* sg1 = sm + 4928; float* sbe1 = sm + 4992;
    float* sg2 = sm + 5056; float* sbe2 = sm + 5120;
    float* sw3 = sm + 5184;

    const int tid = threadIdx.x;

    if (tid < 128) {   // BF0: kk=0 only
        int ntp = tid >> 5, ln = tid & 31, gg = ln >> 2, tt = ln & 3;
        int k0 = 2 * tt;
        int n0 = 8 * (2 * ntp) + gg, n1 = 8 * (2 * ntp + 1) + gg;
        BF0[tid] = make_uint4(
            packh2(W0[k0 * 64 + n0],       W0[(k0 + 1) * 64 + n0]),
            packh2(W0[(k0 + 8) * 64 + n0], W0[(k0 + 9) * 64 + n0]),
            packh2(W0[k0 * 64 + n1],       W0[(k0 + 1) * 64 + n1]),
            packh2(W0[(k0 + 8) * 64 + n1], W0[(k0 + 9) * 64 + n1]));
    }
    for (int i = tid; i < 512; i += 256) {   // BF1/BF2: kk=0..3
        int kk = i >> 7, ntp = (i >> 5) & 3, ln = i & 31, gg = ln >> 2, tt = ln & 3;
        int k0 = 16 * kk + 2 * tt;
        int n0 = 8 * (2 * ntp) + gg, n1 = 8 * (2 * ntp + 1) + gg;
        BF1[i] = make_uint4(
            packh2(W1[k0 * 64 + n0],       W1[(k0 + 1) * 64 + n0]),
            packh2(W1[(k0 + 8) * 64 + n0], W1[(k0 + 9) * 64 + n0]),
            packh2(W1[k0 * 64 + n1],       W1[(k0 + 1) * 64 + n1]),
            packh2(W1[(k0 + 8) * 64 + n1], W1[(k0 + 9) * 64 + n1]));
        BF2[i] = make_uint4(
            packh2(W2[k0 * 64 + n0],       W2[(k0 + 1) * 64 + n0]),
            packh2(W2[(k0 + 8) * 64 + n0], W2[(k0 + 9) * 64 + n0]),
            packh2(W2[k0 * 64 + n1],       W2[(k0 + 1) * 64 + n1]),
            packh2(W2[(k0 + 8) * 64 + n1], W2[(k0 + 9) * 64 + n1]));
    }
    if (tid < 64) {
        sb0[tid] = b0[tid]; sb1[tid] = b1[tid]; sb2[tid] = b2[tid];
        sg0[tid] = g0[tid]; sbe0[tid] = be0[tid];
        sg1[tid] = g1[tid]; sbe1[tid] = be1[tid];
        sg2[tid] = g2[tid]; sbe2[tid] = be2[tid];
        sw3[tid] = W3[tid];
    }
    __syncthreads();
    const float b3v = b3[0];

    const int lane = tid & 31, wid = tid >> 5;
    const int pair = wid >> 1, half = wid & 1;
    const int g = lane >> 2, tg = lane & 3;
    const int barid = pair + 1;   // named barriers 1..4

    unsigned* hbu = (unsigned*)(sm + 5248) + pair * (32 * HSTRW);
    float* pstat = sm + 9856 + pair * 128;
    float* pdot  = sm + 10368 + pair * 64;
    const float4* x4 = (const float4*)x;

    const int lrow = lane & 15;
    const int lc4 = ((lane >> 4) & 1) * 4;
    unsigned a_base0 = (unsigned)__cvta_generic_to_shared(&hbu[lrow * HSTRW + lc4]);
    unsigned a_base1 = (unsigned)__cvta_generic_to_shared(&hbu[(16 + lrow) * HSTRW + lc4]);

    const int npairs = gridDim.x * 4;
    for (int base = (blockIdx.x * 4 + pair) * 32; base < n_edges; base += npairs * 32) {
        // gather: warp `half` loads its endpoint's 8 halfs for all 32 rows
        int e = base + lane; if (e >= n_edges) e = n_edges - 1;
        int idx = half ? ei[n_edges + e] : ei[e];
        float4 V0 = x4[2 * idx], V1 = x4[2 * idx + 1];
        *(uint4*)&hbu[lane * HSTRW + half * 4] = make_uint4(
            packh2(V0.x, V0.y), packh2(V0.z, V0.w),
            packh2(V1.x, V1.y), packh2(V1.z, V1.w));
        barpair(barid);

        float d[2][4][4];

        // layer 0: K=16
        init_bias(d, sb0, tg, half);
        mma_layer<1>(d, BF0, a_base0, a_base1, lane, half);
        ln_tanh_pair<true>(d, sg0, sbe0, hbu, pstat, g, tg, half, barid);
        barpair(barid);   // hb stores visible

        // layer 1: K=64
        init_bias(d, sb1, tg, half);
        mma_layer<4>(d, BF1, a_base0, a_base1, lane, half);
        ln_tanh_pair<true>(d, sg1, sbe1, hbu, pstat, g, tg, half, barid);
        barpair(barid);

        // layer 2: K=64 (output stays in registers, f32 tanh)
        init_bias(d, sb2, tg, half);
        mma_layer<4>(d, BF2, a_base0, a_base1, lane, half);
        ln_tanh_pair<false>(d, sg2, sbe2, hbu, pstat, g, tg, half, barid);

        // layer 3: partial dot over this warp's 32 cols, combine across pair
        float pp[2][2];
#pragma unroll
        for (int mt = 0; mt < 2; mt++) {
            float p1 = 0.f, p2 = 0.f;
#pragma unroll
            for (int ntl = 0; ntl < 4; ntl++) {
                float2 w = *(const float2*)&sw3[8 * (4 * half + ntl) + 2 * tg];
                p1 = fmaf(d[mt][ntl][0], w.x, p1); p1 = fmaf(d[mt][ntl][1], w.y, p1);
                p2 = fmaf(d[mt][ntl][2], w.x, p2); p2 = fmaf(d[mt][ntl][3], w.y, p2);
            }
            p1 += __shfl_xor_sync(0xffffffffu, p1, 1); p1 += __shfl_xor_sync(0xffffffffu, p1, 2);
            p2 += __shfl_xor_sync(0xffffffffu, p2, 1); p2 += __shfl_xor_sync(0xffffffffu, p2, 2);
            pp[mt][0] = p1; pp[mt][1] = p2;
            if (tg == 0)
                *(float2*)&pdot[half * 32 + mt * 16 + g * 2] = make_float2(p1, p2);
        }
        barpair(barid);
        if (half == 0 && tg == 0) {
#pragma unroll
            for (int mt = 0; mt < 2; mt++) {
                float2 o = *(const float2*)&pdot[32 + mt * 16 + g * 2];
                int e1 = base + 16 * mt + g, e2 = e1 + 8;
                if (e1 < n_edges) out[e1] = pp[mt][0] + o.x + b3v;
                if (e2 < n_edges) out[e2] = pp[mt][1] + o.y + b3v;
            }
        }
    }
}

extern "C" void kernel_launch(void* const* d_in, const int* in_sizes, int n_in,
                              void* d_out, int out_size) {
    const float* x   = (const float*)d_in[0];
    const int*   ei  = (const int*)d_in[1];
    const float* W0 = (const float*)d_in[2];
    const float* b0 = (const float*)d_in[3];
    const float* g0 = (const float*)d_in[4];
    const float* be0 = (const float*)d_in[5];
    const float* W1 = (const float*)d_in[6];
    const float* b1 = (const float*)d_in[7];
    const float* g1 = (const float*)d_in[8];
    const float* be1 = (const float*)d_in[9];
    const float* W2 = (const float*)d_in[10];
    const float* b2 = (const float*)d_in[11];
    const float* g2 = (const float*)d_in[12];
    const float* be2 = (const float*)d_in[13];
    const float* W3 = (const float*)d_in[14];
    const float* b3 = (const float*)d_in[15];
    float* out = (float*)d_out;

    const int n_edges = in_sizes[1] / 2;
    const size_t smem_bytes = SMEM_FLOATS * sizeof(float);  // ~41.5 KB

    static bool attr_set = false;
    if (!attr_set) {
        cudaFuncSetAttribute(edge_mlp_tc, cudaFuncAttributeMaxDynamicSharedMemorySize,
                             (int)smem_bytes);
        attr_set = true;
    }

    const int threads = 256;
    const int blocks = 148 * 3;  // 3 resident blocks/SM target, grid-stride
    edge_mlp_tc<<<blocks, threads, smem_bytes>>>(x, ei,
                                                 W0, b0, g0, be0,
                                                 W1, b1, g1, be1,
                                                 W2, b2, g2, be2,
                                                 W3, b3, out, n_edges);
}

// round 13
// speedup vs baseline: 1.1353x; 1.1353x over previous
#include <cuda_runtime.h>
#include <cuda_fp16.h>
#include <cstdint>

#define EPS 1e-5f

__device__ __forceinline__ float tanh_fast(float x) {
    float y; asm("tanh.approx.f32 %0,%1;" : "=f"(y) : "f"(x)); return y;
}
__device__ __forceinline__ unsigned tanh2(unsigned v) {
    unsigned y; asm("tanh.approx.f16x2 %0,%1;" : "=r"(y) : "r"(v)); return y;
}
__device__ __forceinline__ unsigned packh2(float a, float b) {
    __half2 h = __floats2half2_rn(a, b);
    return *reinterpret_cast<unsigned*>(&h);
}
__device__ __forceinline__ float2 h2f2(unsigned u) {
    __half2 h = *reinterpret_cast<__half2*>(&u);
    return __half22float2(h);
}

// f16-accumulator MMA: D/C are 2 packed half2 regs.
// c0 = row g, cols {2tg,2tg+1}; c1 = row g+8, same cols.
__device__ __forceinline__ void mma16h(unsigned* d,
                                       unsigned a0, unsigned a1, unsigned a2, unsigned a3,
                                       unsigned b0, unsigned b1) {
    asm volatile(
        "mma.sync.aligned.m16n8k16.row.col.f16.f16.f16.f16 "
        "{%0,%1},{%2,%3,%4,%5},{%6,%7},{%0,%1};"
        : "+r"(d[0]), "+r"(d[1])
        : "r"(a0), "r"(a1), "r"(a2), "r"(a3), "r"(b0), "r"(b1));
}

__device__ __forceinline__ void ldsm4(unsigned& r0, unsigned& r1, unsigned& r2, unsigned& r3,
                                      unsigned addr) {
    asm volatile("ldmatrix.sync.aligned.m8n8.x4.shared.b16 {%0,%1,%2,%3},[%4];"
                 : "=r"(r0), "=r"(r1), "=r"(r2), "=r"(r3) : "r"(addr));
}

// hb row stride: 72 halfs = 36 u32 words (conflict-free, proven R10)
#define HSTRW 36

__device__ __forceinline__ void init_bias_h(unsigned d[2][8][2],
                                            const unsigned* __restrict__ sbh, int tg) {
#pragma unroll
    for (int nt = 0; nt < 8; nt++) {
        unsigned u = sbh[4 * nt + tg];
        d[0][nt][0] = u; d[0][nt][1] = u;
        d[1][nt][0] = u; d[1][nt][1] = u;
    }
}

template <int NKK>
__device__ __forceinline__ void mma_layer_h(unsigned d[2][8][2], const uint4* __restrict__ bf,
                                            unsigned a_base0, unsigned a_base1, int lane) {
#pragma unroll
    for (int kk = 0; kk < NKK; kk++) {
        unsigned A[2][4];
        ldsm4(A[0][0], A[0][1], A[0][2], A[0][3], a_base0 + kk * 32);
        ldsm4(A[1][0], A[1][1], A[1][2], A[1][3], a_base1 + kk * 32);
#pragma unroll
        for (int ntp = 0; ntp < 4; ntp++) {
            uint4 b = bf[(kk * 4 + ntp) * 32 + lane];
            mma16h(d[0][2 * ntp],     A[0][0], A[0][1], A[0][2], A[0][3], b.x, b.y);
            mma16h(d[1][2 * ntp],     A[1][0], A[1][1], A[1][2], A[1][3], b.x, b.y);
            mma16h(d[0][2 * ntp + 1], A[0][0], A[0][1], A[0][2], A[0][3], b.z, b.w);
            mma16h(d[1][2 * ntp + 1], A[1][0], A[1][1], A[1][2], A[1][3], b.z, b.w);
        }
    }
}

// f32 one-pass LN + tanh on fp16-accumulated d; store tanh2 halves to hb (layers 0/1).
__device__ __forceinline__ void ln_store_h(unsigned d[2][8][2],
                                           const float* __restrict__ sg,
                                           const float* __restrict__ sbe,
                                           unsigned* __restrict__ hbu, int g, int tg) {
#pragma unroll
    for (int mt = 0; mt < 2; mt++) {
        float s1 = 0.f, q1 = 0.f, s2 = 0.f, q2 = 0.f;
#pragma unroll
        for (int nt = 0; nt < 8; nt++) {
            float2 lo = h2f2(d[mt][nt][0]);
            float2 hi = h2f2(d[mt][nt][1]);
            s1 += lo.x + lo.y; q1 = fmaf(lo.x, lo.x, q1); q1 = fmaf(lo.y, lo.y, q1);
            s2 += hi.x + hi.y; q2 = fmaf(hi.x, hi.x, q2); q2 = fmaf(hi.y, hi.y, q2);
        }
        s1 += __shfl_xor_sync(0xffffffffu, s1, 1); q1 += __shfl_xor_sync(0xffffffffu, q1, 1);
        s2 += __shfl_xor_sync(0xffffffffu, s2, 1); q2 += __shfl_xor_sync(0xffffffffu, q2, 1);
        s1 += __shfl_xor_sync(0xffffffffu, s1, 2); q1 += __shfl_xor_sync(0xffffffffu, q1, 2);
        s2 += __shfl_xor_sync(0xffffffffu, s2, 2); q2 += __shfl_xor_sync(0xffffffffu, q2, 2);
        float m1 = s1 * (1.f / 64.f), m2 = s2 * (1.f / 64.f);
        float i1 = rsqrtf(fmaf(-m1, m1, q1 * (1.f / 64.f)) + EPS);
        float i2 = rsqrtf(fmaf(-m2, m2, q2 * (1.f / 64.f)) + EPS);
#pragma unroll
        for (int nt = 0; nt < 8; nt++) {
            float2 lo = h2f2(d[mt][nt][0]);
            float2 hi = h2f2(d[mt][nt][1]);
            float2 gg = *(const float2*)&sg[8 * nt + 2 * tg];
            float2 bb = *(const float2*)&sbe[8 * nt + 2 * tg];
            float y0 = fmaf((lo.x - m1) * i1, gg.x, bb.x);
            float y1 = fmaf((lo.y - m1) * i1, gg.y, bb.y);
            float y2 = fmaf((hi.x - m2) * i2, gg.x, bb.x);
            float y3 = fmaf((hi.y - m2) * i2, gg.y, bb.y);
            hbu[(16 * mt + g) * HSTRW + 4 * nt + tg]     = tanh2(packh2(y0, y1));
            hbu[(16 * mt + g + 8) * HSTRW + 4 * nt + tg] = tanh2(packh2(y2, y3));
        }
    }
}

// smem layout (float units):
// BF0 [512] @0 | BF1 [2048] @512 | BF2 [2048] @2560
// sbh0/1/2 (32 u32 each) @4608,4640,4672
// sg0@4704 sbe0@4768 sg1@4832 sbe1@4896 sg2@4960 sbe2@5024 sw3@5088 -> 5152
// hb @5152: 4 warps x 32 rows x 36 words = 4608 -> total 9760
#define SMEM_FLOATS 9760

__global__ __launch_bounds__(128, 5) void edge_mlp_tc(
    const float* __restrict__ x, const int* __restrict__ ei,
    const float* __restrict__ W0, const float* __restrict__ b0,
    const float* __restrict__ g0, const float* __restrict__ be0,
    const float* __restrict__ W1, const float* __restrict__ b1,
    const float* __restrict__ g1, const float* __restrict__ be1,
    const float* __restrict__ W2, const float* __restrict__ b2,
    const float* __restrict__ g2, const float* __restrict__ be2,
    const float* __restrict__ W3, const float* __restrict__ b3,
    float* __restrict__ out, int n_edges)
{
    extern __shared__ float sm[];
    uint4* BF0 = (uint4*)(sm);
    uint4* BF1 = (uint4*)(sm + 512);
    uint4* BF2 = (uint4*)(sm + 2560);
    unsigned* sbh0 = (unsigned*)(sm + 4608);
    unsigned* sbh1 = (unsigned*)(sm + 4640);
    unsigned* sbh2 = (unsigned*)(sm + 4672);
    float* sg0 = sm + 4704; float* sbe0 = sm + 4768;
    float* sg1 = sm + 4832; float* sbe1 = sm + 4896;
    float* sg2 = sm + 4960; float* sbe2 = sm + 5024;
    float* sw3 = sm + 5088;

    const int tid = threadIdx.x;

    // Stage B fragments as uint4 = {frag(nt=2ntp), frag(nt=2ntp+1)} (same layout as R10)
    if (tid < 128) {   // BF0: kk=0 only
        int ntp = tid >> 5, ln = tid & 31, gg = ln >> 2, tt = ln & 3;
        int k0 = 2 * tt;
        int n0 = 8 * (2 * ntp) + gg, n1 = 8 * (2 * ntp + 1) + gg;
        BF0[tid] = make_uint4(
            packh2(W0[k0 * 64 + n0],       W0[(k0 + 1) * 64 + n0]),
            packh2(W0[(k0 + 8) * 64 + n0], W0[(k0 + 9) * 64 + n0]),
            packh2(W0[k0 * 64 + n1],       W0[(k0 + 1) * 64 + n1]),
            packh2(W0[(k0 + 8) * 64 + n1], W0[(k0 + 9) * 64 + n1]));
    }
    for (int i = tid; i < 512; i += 128) {   // BF1/BF2: kk=0..3
        int kk = i >> 7, ntp = (i >> 5) & 3, ln = i & 31, gg = ln >> 2, tt = ln & 3;
        int k0 = 16 * kk + 2 * tt;
        int n0 = 8 * (2 * ntp) + gg, n1 = 8 * (2 * ntp + 1) + gg;
        BF1[i] = make_uint4(
            packh2(W1[k0 * 64 + n0],       W1[(k0 + 1) * 64 + n0]),
            packh2(W1[(k0 + 8) * 64 + n0], W1[(k0 + 9) * 64 + n0]),
            packh2(W1[k0 * 64 + n1],       W1[(k0 + 1) * 64 + n1]),
            packh2(W1[(k0 + 8) * 64 + n1], W1[(k0 + 9) * 64 + n1]));
        BF2[i] = make_uint4(
            packh2(W2[k0 * 64 + n0],       W2[(k0 + 1) * 64 + n0]),
            packh2(W2[(k0 + 8) * 64 + n0], W2[(k0 + 9) * 64 + n0]),
            packh2(W2[k0 * 64 + n1],       W2[(k0 + 1) * 64 + n1]),
            packh2(W2[(k0 + 8) * 64 + n1], W2[(k0 + 9) * 64 + n1]));
    }
    if (tid < 32) {   // packed half2 biases: sbh[4*nt+tg] = {b[8nt+2tg], b[8nt+2tg+1]}
        int nt = tid >> 2, tg4 = tid & 3;
        int n0 = 8 * nt + 2 * tg4;
        sbh0[tid] = packh2(b0[n0], b0[n0 + 1]);
        sbh1[tid] = packh2(b1[n0], b1[n0 + 1]);
        sbh2[tid] = packh2(b2[n0], b2[n0 + 1]);
    }
    if (tid < 64) {
        sg0[tid] = g0[tid]; sbe0[tid] = be0[tid];
        sg1[tid] = g1[tid]; sbe1[tid] = be1[tid];
        sg2[tid] = g2[tid]; sbe2[tid] = be2[tid];
        sw3[tid] = W3[tid];
    }
    __syncthreads();
    const float b3v = b3[0];

    const int lane = tid & 31, wid = tid >> 5;
    const int g = lane >> 2, tg = lane & 3;
    unsigned* hbu = (unsigned*)(sm + 5152) + wid * (32 * HSTRW);
    const float4* x4 = (const float4*)x;

    const int lrow = lane & 15;
    const int lc4 = ((lane >> 4) & 1) * 4;
    unsigned a_base0 = (unsigned)__cvta_generic_to_shared(&hbu[lrow * HSTRW + lc4]);
    unsigned a_base1 = (unsigned)__cvta_generic_to_shared(&hbu[(16 + lrow) * HSTRW + lc4]);

    const int tile_stride = gridDim.x * 4 * 32;
    for (int base = (blockIdx.x * 4 + wid) * 32; base < n_edges; base += tile_stride) {
        // gather 32 edges -> hb row `lane`, 16 halfs
        int e = base + lane; if (e >= n_edges) e = n_edges - 1;
        int si = ei[e], di = ei[n_edges + e];
        float4 A0 = x4[2 * si], A1 = x4[2 * si + 1];
        float4 C0 = x4[2 * di], C1 = x4[2 * di + 1];
        {
            unsigned* hr = &hbu[lane * HSTRW];
            *(uint4*)&hr[0] = make_uint4(packh2(A0.x, A0.y), packh2(A0.z, A0.w),
                                         packh2(A1.x, A1.y), packh2(A1.z, A1.w));
            *(uint4*)&hr[4] = make_uint4(packh2(C0.x, C0.y), packh2(C0.z, C0.w),
                                         packh2(C1.x, C1.y), packh2(C1.z, C1.w));
        }
        __syncwarp();

        unsigned d[2][8][2];

        // layer 0: K=16
        init_bias_h(d, sbh0, tg);
        mma_layer_h<1>(d, BF0, a_base0, a_base1, lane);
        __syncwarp();
        ln_store_h(d, sg0, sbe0, hbu, g, tg);
        __syncwarp();

        // layer 1: K=64
        init_bias_h(d, sbh1, tg);
        mma_layer_h<4>(d, BF1, a_base0, a_base1, lane);
        __syncwarp();
        ln_store_h(d, sg1, sbe1, hbu, g, tg);
        __syncwarp();

        // layer 2: K=64; LN + f32 tanh fused into final dot
        init_bias_h(d, sbh2, tg);
        mma_layer_h<4>(d, BF2, a_base0, a_base1, lane);
        __syncwarp();   // hb reads done -> safe to overwrite next iteration
#pragma unroll
        for (int mt = 0; mt < 2; mt++) {
            float s1 = 0.f, q1 = 0.f, s2 = 0.f, q2 = 0.f;
#pragma unroll
            for (int nt = 0; nt < 8; nt++) {
                float2 lo = h2f2(d[mt][nt][0]);
                float2 hi = h2f2(d[mt][nt][1]);
                s1 += lo.x + lo.y; q1 = fmaf(lo.x, lo.x, q1); q1 = fmaf(lo.y, lo.y, q1);
                s2 += hi.x + hi.y; q2 = fmaf(hi.x, hi.x, q2); q2 = fmaf(hi.y, hi.y, q2);
            }
            s1 += __shfl_xor_sync(0xffffffffu, s1, 1); q1 += __shfl_xor_sync(0xffffffffu, q1, 1);
            s2 += __shfl_xor_sync(0xffffffffu, s2, 1); q2 += __shfl_xor_sync(0xffffffffu, q2, 1);
            s1 += __shfl_xor_sync(0xffffffffu, s1, 2); q1 += __shfl_xor_sync(0xffffffffu, q1, 2);
            s2 += __shfl_xor_sync(0xffffffffu, s2, 2); q2 += __shfl_xor_sync(0xffffffffu, q2, 2);
            float m1 = s1 * (1.f / 64.f), m2 = s2 * (1.f / 64.f);
            float i1 = rsqrtf(fmaf(-m1, m1, q1 * (1.f / 64.f)) + EPS);
            float i2 = rsqrtf(fmaf(-m2, m2, q2 * (1.f / 64.f)) + EPS);
            float p1 = 0.f, p2 = 0.f;
#pragma unroll
            for (int nt = 0; nt < 8; nt++) {
                float2 lo = h2f2(d[mt][nt][0]);
                float2 hi = h2f2(d[mt][nt][1]);
                float2 gg = *(const float2*)&sg2[8 * nt + 2 * tg];
                float2 bb = *(const float2*)&sbe2[8 * nt + 2 * tg];
                float2 w  = *(const float2*)&sw3[8 * nt + 2 * tg];
                float t0 = tanh_fast(fmaf((lo.x - m1) * i1, gg.x, bb.x));
                float t1 = tanh_fast(fmaf((lo.y - m1) * i1, gg.y, bb.y));
                float t2 = tanh_fast(fmaf((hi.x - m2) * i2, gg.x, bb.x));
                float t3 = tanh_fast(fmaf((hi.y - m2) * i2, gg.y, bb.y));
                p1 = fmaf(t0, w.x, p1); p1 = fmaf(t1, w.y, p1);
                p2 = fmaf(t2, w.x, p2); p2 = fmaf(t3, w.y, p2);
            }
            p1 += __shfl_xor_sync(0xffffffffu, p1, 1); p1 += __shfl_xor_sync(0xffffffffu, p1, 2);
            p2 += __shfl_xor_sync(0xffffffffu, p2, 1); p2 += __shfl_xor_sync(0xffffffffu, p2, 2);
            if (tg == 0) {
                int e1 = base + 16 * mt + g, e2 = e1 + 8;
                if (e1 < n_edges) out[e1] = p1 + b3v;
                if (e2 < n_edges) out[e2] = p2 + b3v;
            }
        }
        __syncwarp();
    }
}

extern "C" void kernel_launch(void* const* d_in, const int* in_sizes, int n_in,
                              void* d_out, int out_size) {
    const float* x   = (const float*)d_in[0];
    const int*   ei  = (const int*)d_in[1];
    const float* W0 = (const float*)d_in[2];
    const float* b0 = (const float*)d_in[3];
    const float* g0 = (const float*)d_in[4];
    const float* be0 = (const float*)d_in[5];
    const float* W1 = (const float*)d_in[6];
    const float* b1 = (const float*)d_in[7];
    const float* g1 = (const float*)d_in[8];
    const float* be1 = (const float*)d_in[9];
    const float* W2 = (const float*)d_in[10];
    const float* b2 = (const float*)d_in[11];
    const float* g2 = (const float*)d_in[12];
    const float* be2 = (const float*)d_in[13];
    const float* W3 = (const float*)d_in[14];
    const float* b3 = (const float*)d_in[15];
    float* out = (float*)d_out;

    const int n_edges = in_sizes[1] / 2;
    const size_t smem_bytes = SMEM_FLOATS * sizeof(float);  // ~38.1 KB

    static bool attr_set = false;
    if (!attr_set) {
        cudaFuncSetAttribute(edge_mlp_tc, cudaFuncAttributeMaxDynamicSharedMemorySize,
                             (int)smem_bytes);
        attr_set = true;
    }

    const int threads = 128;
    const int blocks = 148 * 5;  // 5 resident blocks/SM target (20 warps), grid-stride
    edge_mlp_tc<<<blocks, threads, smem_bytes>>>(x, ei,
                                                 W0, b0, g0, be0,
                                                 W1, b1, g1, be1,
                                                 W2, b2, g2, be2,
                                                 W3, b3, out, n_edges);
}

// round 14
// speedup vs baseline: 1.2740x; 1.1222x over previous
#include <cuda_runtime.h>
#include <cuda_fp16.h>
#include <cstdint>

#define EPS 1e-5f

__device__ __forceinline__ float tanh_fast(float x) {
    float y; asm("tanh.approx.f32 %0,%1;" : "=f"(y) : "f"(x)); return y;
}
__device__ __forceinline__ unsigned tanh2(unsigned v) {
    unsigned y; asm("tanh.approx.f16x2 %0,%1;" : "=r"(y) : "r"(v)); return y;
}
__device__ __forceinline__ unsigned packh2(float a, float b) {
    __half2 h = __floats2half2_rn(a, b);
    return *reinterpret_cast<unsigned*>(&h);
}
__device__ __forceinline__ float2 h2f2(unsigned u) {
    __half2 h = *reinterpret_cast<__half2*>(&u);
    return __half22float2(h);
}
__device__ __forceinline__ unsigned hfma2u(unsigned a, unsigned b, unsigned c) {
    __half2 r = __hfma2(*reinterpret_cast<__half2*>(&a),
                        *reinterpret_cast<__half2*>(&b),
                        *reinterpret_cast<__half2*>(&c));
    return *reinterpret_cast<unsigned*>(&r);
}
__device__ __forceinline__ unsigned splat2(float v) {
    __half2 h = __float2half2_rn(v);
    return *reinterpret_cast<unsigned*>(&h);
}

// f16-accumulator MMA: D/C are 2 packed half2 regs.
__device__ __forceinline__ void mma16h(unsigned* d,
                                       unsigned a0, unsigned a1, unsigned a2, unsigned a3,
                                       unsigned b0, unsigned b1) {
    asm volatile(
        "mma.sync.aligned.m16n8k16.row.col.f16.f16.f16.f16 "
        "{%0,%1},{%2,%3,%4,%5},{%6,%7},{%0,%1};"
        : "+r"(d[0]), "+r"(d[1])
        : "r"(a0), "r"(a1), "r"(a2), "r"(a3), "r"(b0), "r"(b1));
}

__device__ __forceinline__ void ldsm4(unsigned& r0, unsigned& r1, unsigned& r2, unsigned& r3,
                                      unsigned addr) {
    asm volatile("ldmatrix.sync.aligned.m8n8.x4.shared.b16 {%0,%1,%2,%3},[%4];"
                 : "=r"(r0), "=r"(r1), "=r"(r2), "=r"(r3) : "r"(addr));
}

// hb row stride: 72 halfs = 36 u32 words (conflict-free, proven)
#define HSTRW 36

__device__ __forceinline__ void init_bias_h(unsigned d[2][8][2],
                                            const unsigned* __restrict__ sbh, int tg) {
#pragma unroll
    for (int nt = 0; nt < 8; nt++) {
        unsigned u = sbh[4 * nt + tg];
        d[0][nt][0] = u; d[0][nt][1] = u;
        d[1][nt][0] = u; d[1][nt][1] = u;
    }
}

template <int NKK>
__device__ __forceinline__ void mma_layer_h(unsigned d[2][8][2], const uint4* __restrict__ bf,
                                            unsigned a_base0, unsigned a_base1, int lane) {
#pragma unroll
    for (int kk = 0; kk < NKK; kk++) {
        unsigned A[2][4];
        ldsm4(A[0][0], A[0][1], A[0][2], A[0][3], a_base0 + kk * 32);
        ldsm4(A[1][0], A[1][1], A[1][2], A[1][3], a_base1 + kk * 32);
#pragma unroll
        for (int ntp = 0; ntp < 4; ntp++) {
            uint4 b = bf[(kk * 4 + ntp) * 32 + lane];
            mma16h(d[0][2 * ntp],     A[0][0], A[0][1], A[0][2], A[0][3], b.x, b.y);
            mma16h(d[1][2 * ntp],     A[1][0], A[1][1], A[1][2], A[1][3], b.x, b.y);
            mma16h(d[0][2 * ntp + 1], A[0][0], A[0][1], A[0][2], A[0][3], b.z, b.w);
            mma16h(d[1][2 * ntp + 1], A[1][0], A[1][1], A[1][2], A[1][3], b.z, b.w);
        }
    }
}

// f32 stats (one-pass), half2 apply: y = hfma2(hfma2(d, I, MI), G2, BE2); tanh2 -> hb.
__device__ __forceinline__ void ln_store_h2(unsigned d[2][8][2],
                                            const unsigned* __restrict__ G2,
                                            const unsigned* __restrict__ BE2,
                                            unsigned* __restrict__ hbu, int g, int tg) {
#pragma unroll
    for (int mt = 0; mt < 2; mt++) {
        float s1 = 0.f, q1 = 0.f, s2 = 0.f, q2 = 0.f;
#pragma unroll
        for (int nt = 0; nt < 8; nt++) {
            float2 lo = h2f2(d[mt][nt][0]);
            float2 hi = h2f2(d[mt][nt][1]);
            s1 += lo.x + lo.y; q1 = fmaf(lo.x, lo.x, q1); q1 = fmaf(lo.y, lo.y, q1);
            s2 += hi.x + hi.y; q2 = fmaf(hi.x, hi.x, q2); q2 = fmaf(hi.y, hi.y, q2);
        }
        s1 += __shfl_xor_sync(0xffffffffu, s1, 1); q1 += __shfl_xor_sync(0xffffffffu, q1, 1);
        s2 += __shfl_xor_sync(0xffffffffu, s2, 1); q2 += __shfl_xor_sync(0xffffffffu, q2, 1);
        s1 += __shfl_xor_sync(0xffffffffu, s1, 2); q1 += __shfl_xor_sync(0xffffffffu, q1, 2);
        s2 += __shfl_xor_sync(0xffffffffu, s2, 2); q2 += __shfl_xor_sync(0xffffffffu, q2, 2);
        float m1 = s1 * (1.f / 64.f), m2 = s2 * (1.f / 64.f);
        float i1 = rsqrtf(fmaf(-m1, m1, q1 * (1.f / 64.f)) + EPS);
        float i2 = rsqrtf(fmaf(-m2, m2, q2 * (1.f / 64.f)) + EPS);
        unsigned I1 = splat2(i1), MI1 = splat2(-m1 * i1);
        unsigned I2 = splat2(i2), MI2 = splat2(-m2 * i2);
#pragma unroll
        for (int nt = 0; nt < 8; nt++) {
            unsigned G = G2[4 * nt + tg], BE = BE2[4 * nt + tg];
            unsigned y0 = hfma2u(hfma2u(d[mt][nt][0], I1, MI1), G, BE);
            unsigned y1 = hfma2u(hfma2u(d[mt][nt][1], I2, MI2), G, BE);
            hbu[(16 * mt + g) * HSTRW + 4 * nt + tg]     = tanh2(y0);
            hbu[(16 * mt + g + 8) * HSTRW + 4 * nt + tg] = tanh2(y1);
        }
    }
}

// smem layout (float units):
// BF0 [512] @0 | BF1 [2048] @512 | BF2 [2048] @2560
// sbh0/1/2 (32 u32) @4608,4640,4672
// G2_0@4704 BE2_0@4736 G2_1@4768 BE2_1@4800 (32 u32 each)
// sg2@4832 sbe2@4896 sw3@4960 (64 f32 each) -> 5024
// hb @5024: 4 warps x 32 rows x 36 words = 4608 -> total 9632
#define SMEM_FLOATS 9632

__global__ __launch_bounds__(128, 5) void edge_mlp_tc(
    const float* __restrict__ x, const int* __restrict__ ei,
    const float* __restrict__ W0, const float* __restrict__ b0,
    const float* __restrict__ g0, const float* __restrict__ be0,
    const float* __restrict__ W1, const float* __restrict__ b1,
    const float* __restrict__ g1, const float* __restrict__ be1,
    const float* __restrict__ W2, const float* __restrict__ b2,
    const float* __restrict__ g2, const float* __restrict__ be2,
    const float* __restrict__ W3, const float* __restrict__ b3,
    float* __restrict__ out, int n_edges)
{
    extern __shared__ float sm[];
    uint4* BF0 = (uint4*)(sm);
    uint4* BF1 = (uint4*)(sm + 512);
    uint4* BF2 = (uint4*)(sm + 2560);
    unsigned* sbh0 = (unsigned*)(sm + 4608);
    unsigned* sbh1 = (unsigned*)(sm + 4640);
    unsigned* sbh2 = (unsigned*)(sm + 4672);
    unsigned* G2_0 = (unsigned*)(sm + 4704);
    unsigned* BE2_0 = (unsigned*)(sm + 4736);
    unsigned* G2_1 = (unsigned*)(sm + 4768);
    unsigned* BE2_1 = (unsigned*)(sm + 4800);
    float* sg2 = sm + 4832; float* sbe2 = sm + 4896;
    float* sw3 = sm + 4960;

    const int tid = threadIdx.x;

    if (tid < 128) {   // BF0: kk=0 only
        int ntp = tid >> 5, ln = tid & 31, gg = ln >> 2, tt = ln & 3;
        int k0 = 2 * tt;
        int n0 = 8 * (2 * ntp) + gg, n1 = 8 * (2 * ntp + 1) + gg;
        BF0[tid] = make_uint4(
            packh2(W0[k0 * 64 + n0],       W0[(k0 + 1) * 64 + n0]),
            packh2(W0[(k0 + 8) * 64 + n0], W0[(k0 + 9) * 64 + n0]),
            packh2(W0[k0 * 64 + n1],       W0[(k0 + 1) * 64 + n1]),
            packh2(W0[(k0 + 8) * 64 + n1], W0[(k0 + 9) * 64 + n1]));
    }
    for (int i = tid; i < 512; i += 128) {   // BF1/BF2: kk=0..3
        int kk = i >> 7, ntp = (i >> 5) & 3, ln = i & 31, gg = ln >> 2, tt = ln & 3;
        int k0 = 16 * kk + 2 * tt;
        int n0 = 8 * (2 * ntp) + gg, n1 = 8 * (2 * ntp + 1) + gg;
        BF1[i] = make_uint4(
            packh2(W1[k0 * 64 + n0],       W1[(k0 + 1) * 64 + n0]),
            packh2(W1[(k0 + 8) * 64 + n0], W1[(k0 + 9) * 64 + n0]),
            packh2(W1[k0 * 64 + n1],       W1[(k0 + 1) * 64 + n1]),
            packh2(W1[(k0 + 8) * 64 + n1], W1[(k0 + 9) * 64 + n1]));
        BF2[i] = make_uint4(
            packh2(W2[k0 * 64 + n0],       W2[(k0 + 1) * 64 + n0]),
            packh2(W2[(k0 + 8) * 64 + n0], W2[(k0 + 9) * 64 + n0]),
            packh2(W2[k0 * 64 + n1],       W2[(k0 + 1) * 64 + n1]),
            packh2(W2[(k0 + 8) * 64 + n1], W2[(k0 + 9) * 64 + n1]));
    }
    if (tid < 32) {   // packed half2 params, layout [4*nt+tg] -> cols {8nt+2tg, 8nt+2tg+1}
        int nt = tid >> 2, tg4 = tid & 3;
        int n0 = 8 * nt + 2 * tg4;
        sbh0[tid] = packh2(b0[n0], b0[n0 + 1]);
        sbh1[tid] = packh2(b1[n0], b1[n0 + 1]);
        sbh2[tid] = packh2(b2[n0], b2[n0 + 1]);
        G2_0[tid]  = packh2(g0[n0], g0[n0 + 1]);
        BE2_0[tid] = packh2(be0[n0], be0[n0 + 1]);
        G2_1[tid]  = packh2(g1[n0], g1[n0 + 1]);
        BE2_1[tid] = packh2(be1[n0], be1[n0 + 1]);
    }
    if (tid < 64) {
        sg2[tid] = g2[tid]; sbe2[tid] = be2[tid]; sw3[tid] = W3[tid];
    }
    __syncthreads();
    const float b3v = b3[0];

    const int lane = tid & 31, wid = tid >> 5;
    const int g = lane >> 2, tg = lane & 3;
    unsigned* hbu = (unsigned*)(sm + 5024) + wid * (32 * HSTRW);
    const float4* x4 = (const float4*)x;

    const int lrow = lane & 15;
    const int lc4 = ((lane >> 4) & 1) * 4;
    unsigned a_base0 = (unsigned)__cvta_generic_to_shared(&hbu[lrow * HSTRW + lc4]);
    unsigned a_base1 = (unsigned)__cvta_generic_to_shared(&hbu[(16 + lrow) * HSTRW + lc4]);

    const int tile_stride = gridDim.x * 4 * 32;
    for (int base = (blockIdx.x * 4 + wid) * 32; base < n_edges; base += tile_stride) {
        // gather 32 edges -> hb row `lane`, 16 halfs
        int e = base + lane; if (e >= n_edges) e = n_edges - 1;
        int si = ei[e], di = ei[n_edges + e];
        float4 A0 = x4[2 * si], A1 = x4[2 * si + 1];
        float4 C0 = x4[2 * di], C1 = x4[2 * di + 1];
        {
            unsigned* hr = &hbu[lane * HSTRW];
            *(uint4*)&hr[0] = make_uint4(packh2(A0.x, A0.y), packh2(A0.z, A0.w),
                                         packh2(A1.x, A1.y), packh2(A1.z, A1.w));
            *(uint4*)&hr[4] = make_uint4(packh2(C0.x, C0.y), packh2(C0.z, C0.w),
                                         packh2(C1.x, C1.y), packh2(C1.z, C1.w));
        }
        __syncwarp();

        unsigned d[2][8][2];

        // layer 0: K=16
        init_bias_h(d, sbh0, tg);
        mma_layer_h<1>(d, BF0, a_base0, a_base1, lane);
        __syncwarp();
        ln_store_h2(d, G2_0, BE2_0, hbu, g, tg);
        __syncwarp();

        // layer 1: K=64
        init_bias_h(d, sbh1, tg);
        mma_layer_h<4>(d, BF1, a_base0, a_base1, lane);
        __syncwarp();
        ln_store_h2(d, G2_1, BE2_1, hbu, g, tg);
        __syncwarp();

        // layer 2: K=64; f32 LN + tanh fused into final dot (output protected)
        init_bias_h(d, sbh2, tg);
        mma_layer_h<4>(d, BF2, a_base0, a_base1, lane);
        __syncwarp();   // hb reads done -> safe to overwrite next iteration
#pragma unroll
        for (int mt = 0; mt < 2; mt++) {
            float s1 = 0.f, q1 = 0.f, s2 = 0.f, q2 = 0.f;
#pragma unroll
            for (int nt = 0; nt < 8; nt++) {
                float2 lo = h2f2(d[mt][nt][0]);
                float2 hi = h2f2(d[mt][nt][1]);
                s1 += lo.x + lo.y; q1 = fmaf(lo.x, lo.x, q1); q1 = fmaf(lo.y, lo.y, q1);
                s2 += hi.x + hi.y; q2 = fmaf(hi.x, hi.x, q2); q2 = fmaf(hi.y, hi.y, q2);
            }
            s1 += __shfl_xor_sync(0xffffffffu, s1, 1); q1 += __shfl_xor_sync(0xffffffffu, q1, 1);
            s2 += __shfl_xor_sync(0xffffffffu, s2, 1); q2 += __shfl_xor_sync(0xffffffffu, q2, 1);
            s1 += __shfl_xor_sync(0xffffffffu, s1, 2); q1 += __shfl_xor_sync(0xffffffffu, q1, 2);
            s2 += __shfl_xor_sync(0xffffffffu, s2, 2); q2 += __shfl_xor_sync(0xffffffffu, q2, 2);
            float m1 = s1 * (1.f / 64.f), m2 = s2 * (1.f / 64.f);
            float i1 = rsqrtf(fmaf(-m1, m1, q1 * (1.f / 64.f)) + EPS);
            float i2 = rsqrtf(fmaf(-m2, m2, q2 * (1.f / 64.f)) + EPS);
            float p1 = 0.f, p2 = 0.f;
#pragma unroll
            for (int nt = 0; nt < 8; nt++) {
                float2 lo = h2f2(d[mt][nt][0]);
                float2 hi = h2f2(d[mt][nt][1]);
                float2 gg = *(const float2*)&sg2[8 * nt + 2 * tg];
                float2 bb = *(const float2*)&sbe2[8 * nt + 2 * tg];
                float2 w  = *(const float2*)&sw3[8 * nt + 2 * tg];
                float t0 = tanh_fast(fmaf((lo.x - m1) * i1, gg.x, bb.x));
                float t1 = tanh_fast(fmaf((lo.y - m1) * i1, gg.y, bb.y));
                float t2 = tanh_fast(fmaf((hi.x - m2) * i2, gg.x, bb.x));
                float t3 = tanh_fast(fmaf((hi.y - m2) * i2, gg.y, bb.y));
                p1 = fmaf(t0, w.x, p1); p1 = fmaf(t1, w.y, p1);
                p2 = fmaf(t2, w.x, p2); p2 = fmaf(t3, w.y, p2);
            }
            p1 += __shfl_xor_sync(0xffffffffu, p1, 1); p1 += __shfl_xor_sync(0xffffffffu, p1, 2);
            p2 += __shfl_xor_sync(0xffffffffu, p2, 1); p2 += __shfl_xor_sync(0xffffffffu, p2, 2);
            if (tg == 0) {
                int e1 = base + 16 * mt + g, e2 = e1 + 8;
                if (e1 < n_edges) out[e1] = p1 + b3v;
                if (e2 < n_edges) out[e2] = p2 + b3v;
            }
        }
        __syncwarp();
    }
}

extern "C" void kernel_launch(void* const* d_in, const int* in_sizes, int n_in,
                              void* d_out, int out_size) {
    const float* x   = (const float*)d_in[0];
    const int*   ei  = (const int*)d_in[1];
    const float* W0 = (const float*)d_in[2];
    const float* b0 = (const float*)d_in[3];
    const float* g0 = (const float*)d_in[4];
    const float* be0 = (const float*)d_in[5];
    const float* W1 = (const float*)d_in[6];
    const float* b1 = (const float*)d_in[7];
    const float* g1 = (const float*)d_in[8];
    const float* be1 = (const float*)d_in[9];
    const float* W2 = (const float*)d_in[10];
    const float* b2 = (const float*)d_in[11];
    const float* g2 = (const float*)d_in[12];
    const float* be2 = (const float*)d_in[13];
    const float* W3 = (const float*)d_in[14];
    const float* b3 = (const float*)d_in[15];
    float* out = (float*)d_out;

    const int n_edges = in_sizes[1] / 2;
    const size_t smem_bytes = SMEM_FLOATS * sizeof(float);  // ~37.6 KB

    static bool attr_set = false;
    if (!attr_set) {
        cudaFuncSetAttribute(edge_mlp_tc, cudaFuncAttributeMaxDynamicSharedMemorySize,
                             (int)smem_bytes);
        attr_set = true;
    }

    const int threads = 128;
    const int blocks = 148 * 5;  // 5 resident blocks/SM target (20 warps), grid-stride
    edge_mlp_tc<<<blocks, threads, smem_bytes>>>(x, ei,
                                                 W0, b0, g0, be0,
                                                 W1, b1, g1, be1,
                                                 W2, b2, g2, be2,
                                                 W3, b3, out, n_edges);
}

// round 15
// speedup vs baseline: 1.3251x; 1.0401x over previous
#include <cuda_runtime.h>
#include <cuda_fp16.h>
#include <cstdint>

#define EPS 1e-5f

__device__ __forceinline__ unsigned tanh2(unsigned v) {
    unsigned y; asm("tanh.approx.f16x2 %0,%1;" : "=r"(y) : "r"(v)); return y;
}
__device__ __forceinline__ unsigned packh2(float a, float b) {
    __half2 h = __floats2half2_rn(a, b);
    return *reinterpret_cast<unsigned*>(&h);
}
__device__ __forceinline__ float2 h2f2(unsigned u) {
    __half2 h = *reinterpret_cast<__half2*>(&u);
    return __half22float2(h);
}
__device__ __forceinline__ unsigned hfma2u(unsigned a, unsigned b, unsigned c) {
    __half2 r = __hfma2(*reinterpret_cast<__half2*>(&a),
                        *reinterpret_cast<__half2*>(&b),
                        *reinterpret_cast<__half2*>(&c));
    return *reinterpret_cast<unsigned*>(&r);
}
__device__ __forceinline__ unsigned hadd2u(unsigned a, unsigned b) {
    __half2 r = __hadd2(*reinterpret_cast<__half2*>(&a), *reinterpret_cast<__half2*>(&b));
    return *reinterpret_cast<unsigned*>(&r);
}
__device__ __forceinline__ unsigned hmul2u(unsigned a, unsigned b) {
    __half2 r = __hmul2(*reinterpret_cast<__half2*>(&a), *reinterpret_cast<__half2*>(&b));
    return *reinterpret_cast<unsigned*>(&r);
}
__device__ __forceinline__ unsigned splat2(float v) {
    __half2 h = __float2half2_rn(v);
    return *reinterpret_cast<unsigned*>(&h);
}

// f16-accumulator MMA: D/C are 2 packed half2 regs.
__device__ __forceinline__ void mma16h(unsigned* d,
                                       unsigned a0, unsigned a1, unsigned a2, unsigned a3,
                                       unsigned b0, unsigned b1) {
    asm volatile(
        "mma.sync.aligned.m16n8k16.row.col.f16.f16.f16.f16 "
        "{%0,%1},{%2,%3,%4,%5},{%6,%7},{%0,%1};"
        : "+r"(d[0]), "+r"(d[1])
        : "r"(a0), "r"(a1), "r"(a2), "r"(a3), "r"(b0), "r"(b1));
}

__device__ __forceinline__ void ldsm4(unsigned& r0, unsigned& r1, unsigned& r2, unsigned& r3,
                                      unsigned addr) {
    asm volatile("ldmatrix.sync.aligned.m8n8.x4.shared.b16 {%0,%1,%2,%3},[%4];"
                 : "=r"(r0), "=r"(r1), "=r"(r2), "=r"(r3) : "r"(addr));
}

// hb row stride: 72 halfs = 36 u32 words (conflict-free, proven)
#define HSTRW 36

__device__ __forceinline__ void init_bias_h(unsigned d[2][8][2],
                                            const unsigned* __restrict__ sbh, int tg) {
#pragma unroll
    for (int nt = 0; nt < 8; nt++) {
        unsigned u = sbh[4 * nt + tg];
        d[0][nt][0] = u; d[0][nt][1] = u;
        d[1][nt][0] = u; d[1][nt][1] = u;
    }
}

template <int NKK>
__device__ __forceinline__ void mma_layer_h(unsigned d[2][8][2], const uint4* __restrict__ bf,
                                            unsigned a_base0, unsigned a_base1, int lane) {
#pragma unroll
    for (int kk = 0; kk < NKK; kk++) {
        unsigned A[2][4];
        ldsm4(A[0][0], A[0][1], A[0][2], A[0][3], a_base0 + kk * 32);
        ldsm4(A[1][0], A[1][1], A[1][2], A[1][3], a_base1 + kk * 32);
#pragma unroll
        for (int ntp = 0; ntp < 4; ntp++) {
            uint4 b = bf[(kk * 4 + ntp) * 32 + lane];
            mma16h(d[0][2 * ntp],     A[0][0], A[0][1], A[0][2], A[0][3], b.x, b.y);
            mma16h(d[1][2 * ntp],     A[1][0], A[1][1], A[1][2], A[1][3], b.x, b.y);
            mma16h(d[0][2 * ntp + 1], A[0][0], A[0][1], A[0][2], A[0][3], b.z, b.w);
            mma16h(d[1][2 * ntp + 1], A[1][0], A[1][1], A[1][2], A[1][3], b.z, b.w);
        }
    }
}

// half2 stats trees (unpack once), half2 apply, tanh2 -> hb. Layers 0/1.
__device__ __forceinline__ void ln_store_h2(unsigned d[2][8][2],
                                            const unsigned* __restrict__ G2,
                                            const unsigned* __restrict__ BE2,
                                            unsigned* __restrict__ hbu, int g, int tg) {
#pragma unroll
    for (int mt = 0; mt < 2; mt++) {
        unsigned sa0 = d[mt][0][0], sa1 = d[mt][0][1];
        unsigned qa0 = hmul2u(d[mt][0][0], d[mt][0][0]);
        unsigned qa1 = hmul2u(d[mt][0][1], d[mt][0][1]);
#pragma unroll
        for (int nt = 1; nt < 8; nt++) {
            sa0 = hadd2u(sa0, d[mt][nt][0]);
            sa1 = hadd2u(sa1, d[mt][nt][1]);
            qa0 = hfma2u(d[mt][nt][0], d[mt][nt][0], qa0);
            qa1 = hfma2u(d[mt][nt][1], d[mt][nt][1], qa1);
        }
        float2 fs0 = h2f2(sa0), fq0 = h2f2(qa0);
        float2 fs1 = h2f2(sa1), fq1 = h2f2(qa1);
        float s1 = fs0.x + fs0.y, q1 = fq0.x + fq0.y;
        float s2 = fs1.x + fs1.y, q2 = fq1.x + fq1.y;
        s1 += __shfl_xor_sync(0xffffffffu, s1, 1); q1 += __shfl_xor_sync(0xffffffffu, q1, 1);
        s2 += __shfl_xor_sync(0xffffffffu, s2, 1); q2 += __shfl_xor_sync(0xffffffffu, q2, 1);
        s1 += __shfl_xor_sync(0xffffffffu, s1, 2); q1 += __shfl_xor_sync(0xffffffffu, q1, 2);
        s2 += __shfl_xor_sync(0xffffffffu, s2, 2); q2 += __shfl_xor_sync(0xffffffffu, q2, 2);
        float m1 = s1 * (1.f / 64.f), m2 = s2 * (1.f / 64.f);
        float i1 = rsqrtf(fmaf(-m1, m1, q1 * (1.f / 64.f)) + EPS);
        float i2 = rsqrtf(fmaf(-m2, m2, q2 * (1.f / 64.f)) + EPS);
        unsigned I1 = splat2(i1), MI1 = splat2(-m1 * i1);
        unsigned I2 = splat2(i2), MI2 = splat2(-m2 * i2);
#pragma unroll
        for (int nt = 0; nt < 8; nt++) {
            unsigned G = G2[4 * nt + tg], BE = BE2[4 * nt + tg];
            unsigned y0 = hfma2u(hfma2u(d[mt][nt][0], I1, MI1), G, BE);
            unsigned y1 = hfma2u(hfma2u(d[mt][nt][1], I2, MI2), G, BE);
            hbu[(16 * mt + g) * HSTRW + 4 * nt + tg]     = tanh2(y0);
            hbu[(16 * mt + g + 8) * HSTRW + 4 * nt + tg] = tanh2(y1);
        }
    }
}

// smem layout (float units):
// BF0 [512] @0 | BF1 [2048] @512 | BF2 [2048] @2560
// sbh0/1/2 (32 u32) @4608,4640,4672
// G2_0@4704 BE2_0@4736 G2_1@4768 BE2_1@4800 G2_2@4832 BE2_2@4864 (32 u32 each)
// sw3@4896 (64 f32) -> 4960
// hb @4960: 4 warps x 32 rows x 36 words = 4608 -> total 9568
#define SMEM_FLOATS 9568

__global__ __launch_bounds__(128, 5) void edge_mlp_tc(
    const float* __restrict__ x, const int* __restrict__ ei,
    const float* __restrict__ W0, const float* __restrict__ b0,
    const float* __restrict__ g0, const float* __restrict__ be0,
    const float* __restrict__ W1, const float* __restrict__ b1,
    const float* __restrict__ g1, const float* __restrict__ be1,
    const float* __restrict__ W2, const float* __restrict__ b2,
    const float* __restrict__ g2, const float* __restrict__ be2,
    const float* __restrict__ W3, const float* __restrict__ b3,
    float* __restrict__ out, int n_edges)
{
    extern __shared__ float sm[];
    uint4* BF0 = (uint4*)(sm);
    uint4* BF1 = (uint4*)(sm + 512);
    uint4* BF2 = (uint4*)(sm + 2560);
    unsigned* sbh0 = (unsigned*)(sm + 4608);
    unsigned* sbh1 = (unsigned*)(sm + 4640);
    unsigned* sbh2 = (unsigned*)(sm + 4672);
    unsigned* G2_0 = (unsigned*)(sm + 4704);
    unsigned* BE2_0 = (unsigned*)(sm + 4736);
    unsigned* G2_1 = (unsigned*)(sm + 4768);
    unsigned* BE2_1 = (unsigned*)(sm + 4800);
    unsigned* G2_2 = (unsigned*)(sm + 4832);
    unsigned* BE2_2 = (unsigned*)(sm + 4864);
    float* sw3 = sm + 4896;

    const int tid = threadIdx.x;

    if (tid < 128) {   // BF0: kk=0 only
        int ntp = tid >> 5, ln = tid & 31, gg = ln >> 2, tt = ln & 3;
        int k0 = 2 * tt;
        int n0 = 8 * (2 * ntp) + gg, n1 = 8 * (2 * ntp + 1) + gg;
        BF0[tid] = make_uint4(
            packh2(W0[k0 * 64 + n0],       W0[(k0 + 1) * 64 + n0]),
            packh2(W0[(k0 + 8) * 64 + n0], W0[(k0 + 9) * 64 + n0]),
            packh2(W0[k0 * 64 + n1],       W0[(k0 + 1) * 64 + n1]),
            packh2(W0[(k0 + 8) * 64 + n1], W0[(k0 + 9) * 64 + n1]));
    }
    for (int i = tid; i < 512; i += 128) {   // BF1/BF2: kk=0..3
        int kk = i >> 7, ntp = (i >> 5) & 3, ln = i & 31, gg = ln >> 2, tt = ln & 3;
        int k0 = 16 * kk + 2 * tt;
        int n0 = 8 * (2 * ntp) + gg, n1 = 8 * (2 * ntp + 1) + gg;
        BF1[i] = make_uint4(
            packh2(W1[k0 * 64 + n0],       W1[(k0 + 1) * 64 + n0]),
            packh2(W1[(k0 + 8) * 64 + n0], W1[(k0 + 9) * 64 + n0]),
            packh2(W1[k0 * 64 + n1],       W1[(k0 + 1) * 64 + n1]),
            packh2(W1[(k0 + 8) * 64 + n1], W1[(k0 + 9) * 64 + n1]));
        BF2[i] = make_uint4(
            packh2(W2[k0 * 64 + n0],       W2[(k0 + 1) * 64 + n0]),
            packh2(W2[(k0 + 8) * 64 + n0], W2[(k0 + 9) * 64 + n0]),
            packh2(W2[k0 * 64 + n1],       W2[(k0 + 1) * 64 + n1]),
            packh2(W2[(k0 + 8) * 64 + n1], W2[(k0 + 9) * 64 + n1]));
    }
    if (tid < 32) {   // packed half2 params, layout [4*nt+tg] -> cols {8nt+2tg, 8nt+2tg+1}
        int nt = tid >> 2, tg4 = tid & 3;
        int n0 = 8 * nt + 2 * tg4;
        sbh0[tid] = packh2(b0[n0], b0[n0 + 1]);
        sbh1[tid] = packh2(b1[n0], b1[n0 + 1]);
        sbh2[tid] = packh2(b2[n0], b2[n0 + 1]);
        G2_0[tid]  = packh2(g0[n0], g0[n0 + 1]);
        BE2_0[tid] = packh2(be0[n0], be0[n0 + 1]);
        G2_1[tid]  = packh2(g1[n0], g1[n0 + 1]);
        BE2_1[tid] = packh2(be1[n0], be1[n0 + 1]);
        G2_2[tid]  = packh2(g2[n0], g2[n0 + 1]);
        BE2_2[tid] = packh2(be2[n0], be2[n0 + 1]);
    }
    if (tid < 64) sw3[tid] = W3[tid];
    __syncthreads();
    const float b3v = b3[0];

    const int lane = tid & 31, wid = tid >> 5;
    const int g = lane >> 2, tg = lane & 3;
    unsigned* hbu = (unsigned*)(sm + 4960) + wid * (32 * HSTRW);
    const float4* x4 = (const float4*)x;

    const int lrow = lane & 15;
    const int lc4 = ((lane >> 4) & 1) * 4;
    unsigned a_base0 = (unsigned)__cvta_generic_to_shared(&hbu[lrow * HSTRW + lc4]);
    unsigned a_base1 = (unsigned)__cvta_generic_to_shared(&hbu[(16 + lrow) * HSTRW + lc4]);

    const int tile_stride = gridDim.x * 4 * 32;
    for (int base = (blockIdx.x * 4 + wid) * 32; base < n_edges; base += tile_stride) {
        // gather 32 edges -> hb row `lane`, 16 halfs
        int e = base + lane; if (e >= n_edges) e = n_edges - 1;
        int si = ei[e], di = ei[n_edges + e];
        float4 A0 = x4[2 * si], A1 = x4[2 * si + 1];
        float4 C0 = x4[2 * di], C1 = x4[2 * di + 1];
        {
            unsigned* hr = &hbu[lane * HSTRW];
            *(uint4*)&hr[0] = make_uint4(packh2(A0.x, A0.y), packh2(A0.z, A0.w),
                                         packh2(A1.x, A1.y), packh2(A1.z, A1.w));
            *(uint4*)&hr[4] = make_uint4(packh2(C0.x, C0.y), packh2(C0.z, C0.w),
                                         packh2(C1.x, C1.y), packh2(C1.z, C1.w));
        }
        __syncwarp();

        unsigned d[2][8][2];

        // layer 0: K=16
        init_bias_h(d, sbh0, tg);
        mma_layer_h<1>(d, BF0, a_base0, a_base1, lane);
        __syncwarp();
        ln_store_h2(d, G2_0, BE2_0, hbu, g, tg);
        __syncwarp();

        // layer 1: K=64
        init_bias_h(d, sbh1, tg);
        mma_layer_h<4>(d, BF1, a_base0, a_base1, lane);
        __syncwarp();
        ln_store_h2(d, G2_1, BE2_1, hbu, g, tg);
        __syncwarp();

        // layer 2: K=64; f32 stats, half2 apply + tanh2, f32 dot (output protected)
        init_bias_h(d, sbh2, tg);
        mma_layer_h<4>(d, BF2, a_base0, a_base1, lane);
        __syncwarp();   // hb reads done -> safe to overwrite next iteration
#pragma unroll
        for (int mt = 0; mt < 2; mt++) {
            float s1 = 0.f, q1 = 0.f, s2 = 0.f, q2 = 0.f;
#pragma unroll
            for (int nt = 0; nt < 8; nt++) {
                float2 lo = h2f2(d[mt][nt][0]);
                float2 hi = h2f2(d[mt][nt][1]);
                s1 += lo.x + lo.y; q1 = fmaf(lo.x, lo.x, q1); q1 = fmaf(lo.y, lo.y, q1);
                s2 += hi.x + hi.y; q2 = fmaf(hi.x, hi.x, q2); q2 = fmaf(hi.y, hi.y, q2);
            }
            s1 += __shfl_xor_sync(0xffffffffu, s1, 1); q1 += __shfl_xor_sync(0xffffffffu, q1, 1);
            s2 += __shfl_xor_sync(0xffffffffu, s2, 1); q2 += __shfl_xor_sync(0xffffffffu, q2, 1);
            s1 += __shfl_xor_sync(0xffffffffu, s1, 2); q1 += __shfl_xor_sync(0xffffffffu, q1, 2);
            s2 += __shfl_xor_sync(0xffffffffu, s2, 2); q2 += __shfl_xor_sync(0xffffffffu, q2, 2);
            float m1 = s1 * (1.f / 64.f), m2 = s2 * (1.f / 64.f);
            float i1 = rsqrtf(fmaf(-m1, m1, q1 * (1.f / 64.f)) + EPS);
            float i2 = rsqrtf(fmaf(-m2, m2, q2 * (1.f / 64.f)) + EPS);
            unsigned I1 = splat2(i1), MI1 = splat2(-m1 * i1);
            unsigned I2 = splat2(i2), MI2 = splat2(-m2 * i2);
            float p1 = 0.f, p2 = 0.f;
#pragma unroll
            for (int nt = 0; nt < 8; nt++) {
                unsigned G = G2_2[4 * nt + tg], BE = BE2_2[4 * nt + tg];
                unsigned y0 = tanh2(hfma2u(hfma2u(d[mt][nt][0], I1, MI1), G, BE));
                unsigned y1 = tanh2(hfma2u(hfma2u(d[mt][nt][1], I2, MI2), G, BE));
                float2 t01 = h2f2(y0), t23 = h2f2(y1);
                float2 w = *(const float2*)&sw3[8 * nt + 2 * tg];
                p1 = fmaf(t01.x, w.x, p1); p1 = fmaf(t01.y, w.y, p1);
                p2 = fmaf(t23.x, w.x, p2); p2 = fmaf(t23.y, w.y, p2);
            }
            p1 += __shfl_xor_sync(0xffffffffu, p1, 1); p1 += __shfl_xor_sync(0xffffffffu, p1, 2);
            p2 += __shfl_xor_sync(0xffffffffu, p2, 1); p2 += __shfl_xor_sync(0xffffffffu, p2, 2);
            if (tg == 0) {
                int e1 = base + 16 * mt + g, e2 = e1 + 8;
                if (e1 < n_edges) out[e1] = p1 + b3v;
                if (e2 < n_edges) out[e2] = p2 + b3v;
            }
        }
        __syncwarp();
    }
}

extern "C" void kernel_launch(void* const* d_in, const int* in_sizes, int n_in,
                              void* d_out, int out_size) {
    const float* x   = (const float*)d_in[0];
    const int*   ei  = (const int*)d_in[1];
    const float* W0 = (const float*)d_in[2];
    const float* b0 = (const float*)d_in[3];
    const float* g0 = (const float*)d_in[4];
    const float* be0 = (const float*)d_in[5];
    const float* W1 = (const float*)d_in[6];
    const float* b1 = (const float*)d_in[7];
    const float* g1 = (const float*)d_in[8];
    const float* be1 = (const float*)d_in[9];
    const float* W2 = (const float*)d_in[10];
    const float* b2 = (const float*)d_in[11];
    const float* g2 = (const float*)d_in[12];
    const float* be2 = (const float*)d_in[13];
    const float* W3 = (const float*)d_in[14];
    const float* b3 = (const float*)d_in[15];
    float* out = (float*)d_out;

    const int n_edges = in_sizes[1] / 2;
    const size_t smem_bytes = SMEM_FLOATS * sizeof(float);  // ~37.4 KB

    static bool attr_set = false;
    if (!attr_set) {
        cudaFuncSetAttribute(edge_mlp_tc, cudaFuncAttributeMaxDynamicSharedMemorySize,
                             (int)smem_bytes);
        attr_set = true;
    }

    const int threads = 128;
    const int blocks = 148 * 5;  // 5 resident blocks/SM target (20 warps), grid-stride
    edge_mlp_tc<<<blocks, threads, smem_bytes>>>(x, ei,
                                                 W0, b0, g0, be0,
                                                 W1, b1, g1, be1,
                                                 W2, b2, g2, be2,
                                                 W3, b3, out, n_edges);
}